// round 1
// baseline (speedup 1.0000x reference)
#include <cuda_runtime.h>
#include <math.h>

#define H_DIM 1024
#define R_DIM 32
#define NAG 256
#define BTOK 8192
#define NTHREADS 256
#define NWARPS 8
#define NB 256          // tokens processed per batch (inter buffer capacity)
#define LN_EPS 1e-5f
#define ALPHA_MAX 5.0f

// Dynamic SMEM layout (floats):
//   buf   [32768]  : U then V (128 KB)
//   inter [NB*32]  : intermediates (32 KB)
//   toks  [8192]   : token index list (32 KB, as int)
#define SMEM_FLOATS (32768 + NB * R_DIM)
#define SMEM_BYTES  (SMEM_FLOATS * 4 + BTOK * 4)

__global__ __launch_bounds__(NTHREADS, 1)
void div_inject_kernel(const float* __restrict__ h,
                       const float* __restrict__ log_alpha,
                       const float* __restrict__ gamma,
                       const float* __restrict__ beta,
                       const float* __restrict__ pu,
                       const float* __restrict__ pv,
                       const int*   __restrict__ ids,
                       float*       __restrict__ out)
{
    extern __shared__ float smem[];
    float* buf   = smem;                       // 32768 floats (U or V)
    float* inter = smem + 32768;               // NB*32 floats
    int*   toks  = (int*)(smem + SMEM_FLOATS); // 8192 ints
    __shared__ int cnt_s;

    const int tid   = threadIdx.x;
    const int lane  = tid & 31;
    const int wid   = tid >> 5;
    const int agent = blockIdx.x;

    // ---- 1. scan agent_ids, collect this agent's tokens ----
    if (tid == 0) cnt_s = 0;
    __syncthreads();
    for (int i = tid; i < BTOK; i += NTHREADS) {
        if ((ids[i] & (NAG - 1)) == agent) {
            int p = atomicAdd(&cnt_s, 1);
            toks[p] = i;
        }
    }
    __syncthreads();
    const int total = cnt_s;
    if (total == 0) return;

    float la = log_alpha[0];
    const float alpha = fminf(expf(la), ALPHA_MAX);

    for (int base = 0; base < total; base += NB) {
        const int nb = min(NB, total - base);

        // ---- 2. load U[agent] (H x R row-major) into SMEM ----
        {
            const float4* src = (const float4*)(pu + (size_t)agent * (H_DIM * R_DIM));
            float4* dst = (float4*)buf;
            #pragma unroll 4
            for (int i = tid; i < (H_DIM * R_DIM) / 4; i += NTHREADS) dst[i] = src[i];
        }
        __syncthreads();

        // ---- 3. phase A: inter[t][r] = sum_k h[t][k] * U[k][r] ----
        // warp handles 4 tokens; lane = r
        for (int ti0 = wid * 4; ti0 < nb; ti0 += NWARPS * 4) {
            const int j1 = min(ti0 + 1, nb - 1);
            const int j2 = min(ti0 + 2, nb - 1);
            const int j3 = min(ti0 + 3, nb - 1);
            const float4* h0 = (const float4*)(h + (size_t)toks[base + ti0] * H_DIM);
            const float4* h1 = (const float4*)(h + (size_t)toks[base + j1]  * H_DIM);
            const float4* h2 = (const float4*)(h + (size_t)toks[base + j2]  * H_DIM);
            const float4* h3 = (const float4*)(h + (size_t)toks[base + j3]  * H_DIM);

            // per-component accumulators -> 16 independent FFMA chains
            float a0x=0.f,a0y=0.f,a0z=0.f,a0w=0.f;
            float a1x=0.f,a1y=0.f,a1z=0.f,a1w=0.f;
            float a2x=0.f,a2y=0.f,a2z=0.f,a2w=0.f;
            float a3x=0.f,a3y=0.f,a3z=0.f,a3w=0.f;

            #pragma unroll 4
            for (int k4 = 0; k4 < H_DIM / 4; ++k4) {
                float4 x0 = h0[k4];
                float4 x1 = h1[k4];
                float4 x2 = h2[k4];
                float4 x3 = h3[k4];
                const float* up = buf + k4 * 4 * R_DIM + lane;
                float u0 = up[0];
                float u1 = up[R_DIM];
                float u2 = up[2 * R_DIM];
                float u3 = up[3 * R_DIM];
                a0x = fmaf(x0.x, u0, a0x); a0y = fmaf(x0.y, u1, a0y);
                a0z = fmaf(x0.z, u2, a0z); a0w = fmaf(x0.w, u3, a0w);
                a1x = fmaf(x1.x, u0, a1x); a1y = fmaf(x1.y, u1, a1y);
                a1z = fmaf(x1.z, u2, a1z); a1w = fmaf(x1.w, u3, a1w);
                a2x = fmaf(x2.x, u0, a2x); a2y = fmaf(x2.y, u1, a2y);
                a2z = fmaf(x2.z, u2, a2z); a2w = fmaf(x2.w, u3, a2w);
                a3x = fmaf(x3.x, u0, a3x); a3y = fmaf(x3.y, u1, a3y);
                a3z = fmaf(x3.z, u2, a3z); a3w = fmaf(x3.w, u3, a3w);
            }
            inter[ti0 * R_DIM + lane] = a0x + a0y + a0z + a0w;
            if (ti0 + 1 < nb) inter[(ti0 + 1) * R_DIM + lane] = a1x + a1y + a1z + a1w;
            if (ti0 + 2 < nb) inter[(ti0 + 2) * R_DIM + lane] = a2x + a2y + a2z + a2w;
            if (ti0 + 3 < nb) inter[(ti0 + 3) * R_DIM + lane] = a3x + a3y + a3z + a3w;
        }
        __syncthreads();

        // ---- 4. load V[agent] (R x H row-major) into SMEM (overwrite U) ----
        {
            const float4* src = (const float4*)(pv + (size_t)agent * (R_DIM * H_DIM));
            float4* dst = (float4*)buf;
            #pragma unroll 4
            for (int i = tid; i < (R_DIM * H_DIM) / 4; i += NTHREADS) dst[i] = src[i];
        }
        __syncthreads();

        // ---- 5. phase B: pert[t][j] = sum_r inter[t][r] * V[r][j]; residual + LN ----
        // warp handles 2 tokens; lane owns float4 groups g = lane + 32*m, m=0..7
        for (int ti0 = wid * 2; ti0 < nb; ti0 += NWARPS * 2) {
            const bool two = (ti0 + 1) < nb;
            const int ji = min(ti0 + 1, nb - 1);
            const int t0 = toks[base + ti0];
            const int t1 = toks[base + ji];
            const float iv0 = inter[ti0 * R_DIM + lane];
            const float iv1 = inter[ji * R_DIM + lane];

            float4 acc0[8], acc1[8];
            #pragma unroll
            for (int m = 0; m < 8; ++m) {
                acc0[m] = make_float4(0.f, 0.f, 0.f, 0.f);
                acc1[m] = make_float4(0.f, 0.f, 0.f, 0.f);
            }

            const float4* vs = (const float4*)buf;
            #pragma unroll 4
            for (int r = 0; r < R_DIM; ++r) {
                const float b0 = __shfl_sync(0xffffffffu, iv0, r);
                const float b1 = __shfl_sync(0xffffffffu, iv1, r);
                const float4* vr = vs + r * (H_DIM / 4) + lane;
                #pragma unroll
                for (int m = 0; m < 8; ++m) {
                    float4 vv = vr[m * 32];
                    acc0[m].x = fmaf(b0, vv.x, acc0[m].x);
                    acc0[m].y = fmaf(b0, vv.y, acc0[m].y);
                    acc0[m].z = fmaf(b0, vv.z, acc0[m].z);
                    acc0[m].w = fmaf(b0, vv.w, acc0[m].w);
                    acc1[m].x = fmaf(b1, vv.x, acc1[m].x);
                    acc1[m].y = fmaf(b1, vv.y, acc1[m].y);
                    acc1[m].z = fmaf(b1, vv.z, acc1[m].z);
                    acc1[m].w = fmaf(b1, vv.w, acc1[m].w);
                }
            }

            // epilogue: residual + LayerNorm, entirely warp-local
            #pragma unroll
            for (int pass = 0; pass < 2; ++pass) {
                if (pass == 1 && !two) break;
                const int t = (pass == 0) ? t0 : t1;
                float4* acc = (pass == 0) ? acc0 : acc1;

                const float4* hq = (const float4*)(h + (size_t)t * H_DIM);
                float s = 0.f, sq = 0.f;
                #pragma unroll
                for (int m = 0; m < 8; ++m) {
                    float4 hv = hq[lane + 32 * m];
                    float4 d;
                    d.x = fmaf(alpha, acc[m].x, hv.x);
                    d.y = fmaf(alpha, acc[m].y, hv.y);
                    d.z = fmaf(alpha, acc[m].z, hv.z);
                    d.w = fmaf(alpha, acc[m].w, hv.w);
                    acc[m] = d;
                    s  += d.x + d.y + d.z + d.w;
                    sq += d.x * d.x + d.y * d.y + d.z * d.z + d.w * d.w;
                }
                #pragma unroll
                for (int o = 16; o > 0; o >>= 1) {
                    s  += __shfl_xor_sync(0xffffffffu, s,  o);
                    sq += __shfl_xor_sync(0xffffffffu, sq, o);
                }
                const float mean = s * (1.0f / H_DIM);
                const float var  = sq * (1.0f / H_DIM) - mean * mean;
                const float rstd = rsqrtf(var + LN_EPS);

                float4* op = (float4*)(out + (size_t)t * H_DIM);
                const float4* g4 = (const float4*)gamma;
                const float4* b4 = (const float4*)beta;
                #pragma unroll
                for (int m = 0; m < 8; ++m) {
                    float4 g = g4[lane + 32 * m];
                    float4 bb = b4[lane + 32 * m];
                    float4 o_;
                    o_.x = (acc[m].x - mean) * rstd * g.x + bb.x;
                    o_.y = (acc[m].y - mean) * rstd * g.y + bb.y;
                    o_.z = (acc[m].z - mean) * rstd * g.z + bb.z;
                    o_.w = (acc[m].w - mean) * rstd * g.w + bb.w;
                    op[lane + 32 * m] = o_;
                }
            }
        }
        __syncthreads();
    }
}

extern "C" void kernel_launch(void* const* d_in, const int* in_sizes, int n_in,
                              void* d_out, int out_size)
{
    const float* h     = (const float*)d_in[0];
    const float* la    = (const float*)d_in[1];
    const float* gamma = (const float*)d_in[2];
    const float* beta  = (const float*)d_in[3];
    const float* pu    = (const float*)d_in[4];
    const float* pv    = (const float*)d_in[5];
    const int*   ids   = (const int*)d_in[6];
    float*       out   = (float*)d_out;

    cudaFuncSetAttribute(div_inject_kernel,
                         cudaFuncAttributeMaxDynamicSharedMemorySize, SMEM_BYTES);
    div_inject_kernel<<<NAG, NTHREADS, SMEM_BYTES>>>(h, la, gamma, beta, pu, pv, ids, out);
}

// round 2
// speedup vs baseline: 1.3967x; 1.3967x over previous
#include <cuda_runtime.h>
#include <math.h>

#define H_DIM 1024
#define R_DIM 32
#define NAG 256
#define BTOK 8192
#define NTH 512
#define NW 16
#define TB 64             // tokens per batch
#define LN_EPS 1e-5f
#define ALPHA_MAX 5.0f

// Global scratch (device statics are the allowed scratch mechanism)
__device__ int g_cnt[NAG];
__device__ int g_toks[NAG][BTOK];

__global__ void zero_cnt_kernel() {
    g_cnt[threadIdx.x] = 0;
}

__global__ void build_lists_kernel(const int* __restrict__ ids) {
    int i = blockIdx.x * blockDim.x + threadIdx.x;
    if (i < BTOK) {
        int a = ids[i] & (NAG - 1);
        int p = atomicAdd(&g_cnt[a], 1);
        g_toks[a][p] = i;
    }
}

// SMEM: buf 32768 floats (U or V, 128 KB) + inter TB*32 floats + stoks TB ints
#define SMEM_BYTES ((32768 + TB * R_DIM) * 4 + TB * 4)

__global__ __launch_bounds__(NTH, 1)
void div_inject_kernel(const float* __restrict__ h,
                       const float* __restrict__ log_alpha,
                       const float* __restrict__ gamma,
                       const float* __restrict__ beta,
                       const float* __restrict__ pu,
                       const float* __restrict__ pv,
                       float*       __restrict__ out)
{
    extern __shared__ float smem[];
    float* buf   = smem;                          // 32768 floats
    float* inter = smem + 32768;                  // TB*32 floats
    int*   stoks = (int*)(smem + 32768 + TB * R_DIM);

    const int tid   = threadIdx.x;
    const int lane  = tid & 31;
    const int wid   = tid >> 5;
    const int agent = blockIdx.x;

    const int total = g_cnt[agent];
    if (total == 0) return;
    const int* toks = g_toks[agent];

    const float alpha = fminf(expf(log_alpha[0]), ALPHA_MAX);

    for (int base = 0; base < total; base += TB) {
        const int nb = min(TB, total - base);

        // stage this batch's token ids into smem
        if (tid < nb) stoks[tid] = toks[base + tid];

        // ---- load U[agent] (H x R row-major, 128 KB) into SMEM ----
        {
            const float4* src = (const float4*)(pu + (size_t)agent * (H_DIM * R_DIM));
            float4* dst = (float4*)buf;
            #pragma unroll 4
            for (int i = tid; i < (H_DIM * R_DIM) / 4; i += NTH) dst[i] = src[i];
        }
        __syncthreads();

        // ---- phase A: inter[t][r] = sum_k h[t][k] * U[k][r] ----
        // warp handles 4 tokens; lane = r
        for (int ti0 = wid * 4; ti0 < nb; ti0 += NW * 4) {
            const int j1 = min(ti0 + 1, nb - 1);
            const int j2 = min(ti0 + 2, nb - 1);
            const int j3 = min(ti0 + 3, nb - 1);
            const float4* h0 = (const float4*)(h + (size_t)stoks[ti0] * H_DIM);
            const float4* h1 = (const float4*)(h + (size_t)stoks[j1]  * H_DIM);
            const float4* h2 = (const float4*)(h + (size_t)stoks[j2]  * H_DIM);
            const float4* h3 = (const float4*)(h + (size_t)stoks[j3]  * H_DIM);

            float a0x=0.f,a0y=0.f,a0z=0.f,a0w=0.f;
            float a1x=0.f,a1y=0.f,a1z=0.f,a1w=0.f;
            float a2x=0.f,a2y=0.f,a2z=0.f,a2w=0.f;
            float a3x=0.f,a3y=0.f,a3z=0.f,a3w=0.f;

            #pragma unroll 4
            for (int k4 = 0; k4 < H_DIM / 4; ++k4) {
                float4 x0 = h0[k4];
                float4 x1 = h1[k4];
                float4 x2 = h2[k4];
                float4 x3 = h3[k4];
                const float* up = buf + k4 * 4 * R_DIM + lane;
                float u0 = up[0];
                float u1 = up[R_DIM];
                float u2 = up[2 * R_DIM];
                float u3 = up[3 * R_DIM];
                a0x = fmaf(x0.x, u0, a0x); a0y = fmaf(x0.y, u1, a0y);
                a0z = fmaf(x0.z, u2, a0z); a0w = fmaf(x0.w, u3, a0w);
                a1x = fmaf(x1.x, u0, a1x); a1y = fmaf(x1.y, u1, a1y);
                a1z = fmaf(x1.z, u2, a1z); a1w = fmaf(x1.w, u3, a1w);
                a2x = fmaf(x2.x, u0, a2x); a2y = fmaf(x2.y, u1, a2y);
                a2z = fmaf(x2.z, u2, a2z); a2w = fmaf(x2.w, u3, a2w);
                a3x = fmaf(x3.x, u0, a3x); a3y = fmaf(x3.y, u1, a3y);
                a3z = fmaf(x3.z, u2, a3z); a3w = fmaf(x3.w, u3, a3w);
            }
            inter[ti0 * R_DIM + lane] = a0x + a0y + a0z + a0w;
            if (ti0 + 1 < nb) inter[(ti0 + 1) * R_DIM + lane] = a1x + a1y + a1z + a1w;
            if (ti0 + 2 < nb) inter[(ti0 + 2) * R_DIM + lane] = a2x + a2y + a2z + a2w;
            if (ti0 + 3 < nb) inter[(ti0 + 3) * R_DIM + lane] = a3x + a3y + a3z + a3w;
        }
        __syncthreads();

        // ---- load V[agent] (R x H row-major, 128 KB) into SMEM (overwrite U) ----
        {
            const float4* src = (const float4*)(pv + (size_t)agent * (R_DIM * H_DIM));
            float4* dst = (float4*)buf;
            #pragma unroll 4
            for (int i = tid; i < (R_DIM * H_DIM) / 4; i += NTH) dst[i] = src[i];
        }
        __syncthreads();

        // ---- phase B: pert + residual + LayerNorm; warp handles 2 tokens ----
        for (int ti0 = wid * 2; ti0 < nb; ti0 += NW * 2) {
            const bool two = (ti0 + 1) < nb;
            const int ji = min(ti0 + 1, nb - 1);
            const int t0 = stoks[ti0];
            const int t1 = stoks[ji];
            const float iv0 = inter[ti0 * R_DIM + lane];
            const float iv1 = inter[ji * R_DIM + lane];

            float4 acc0[8], acc1[8];
            #pragma unroll
            for (int m = 0; m < 8; ++m) {
                acc0[m] = make_float4(0.f, 0.f, 0.f, 0.f);
                acc1[m] = make_float4(0.f, 0.f, 0.f, 0.f);
            }

            const float4* vs = (const float4*)buf;
            #pragma unroll 4
            for (int r = 0; r < R_DIM; ++r) {
                const float b0 = __shfl_sync(0xffffffffu, iv0, r);
                const float b1 = __shfl_sync(0xffffffffu, iv1, r);
                const float4* vr = vs + r * (H_DIM / 4) + lane;
                #pragma unroll
                for (int m = 0; m < 8; ++m) {
                    float4 vv = vr[m * 32];
                    acc0[m].x = fmaf(b0, vv.x, acc0[m].x);
                    acc0[m].y = fmaf(b0, vv.y, acc0[m].y);
                    acc0[m].z = fmaf(b0, vv.z, acc0[m].z);
                    acc0[m].w = fmaf(b0, vv.w, acc0[m].w);
                    acc1[m].x = fmaf(b1, vv.x, acc1[m].x);
                    acc1[m].y = fmaf(b1, vv.y, acc1[m].y);
                    acc1[m].z = fmaf(b1, vv.z, acc1[m].z);
                    acc1[m].w = fmaf(b1, vv.w, acc1[m].w);
                }
            }

            #pragma unroll
            for (int pass = 0; pass < 2; ++pass) {
                if (pass == 1 && !two) break;
                const int t = (pass == 0) ? t0 : t1;
                float4* acc = (pass == 0) ? acc0 : acc1;

                const float4* hq = (const float4*)(h + (size_t)t * H_DIM);
                float s = 0.f, sq = 0.f;
                #pragma unroll
                for (int m = 0; m < 8; ++m) {
                    float4 hv = hq[lane + 32 * m];
                    float4 d;
                    d.x = fmaf(alpha, acc[m].x, hv.x);
                    d.y = fmaf(alpha, acc[m].y, hv.y);
                    d.z = fmaf(alpha, acc[m].z, hv.z);
                    d.w = fmaf(alpha, acc[m].w, hv.w);
                    acc[m] = d;
                    s  += d.x + d.y + d.z + d.w;
                    sq += d.x * d.x + d.y * d.y + d.z * d.z + d.w * d.w;
                }
                #pragma unroll
                for (int o = 16; o > 0; o >>= 1) {
                    s  += __shfl_xor_sync(0xffffffffu, s,  o);
                    sq += __shfl_xor_sync(0xffffffffu, sq, o);
                }
                const float mean = s * (1.0f / H_DIM);
                const float var  = sq * (1.0f / H_DIM) - mean * mean;
                const float rstd = rsqrtf(var + LN_EPS);

                float4* op = (float4*)(out + (size_t)t * H_DIM);
                const float4* g4 = (const float4*)gamma;
                const float4* b4 = (const float4*)beta;
                #pragma unroll
                for (int m = 0; m < 8; ++m) {
                    float4 g = g4[lane + 32 * m];
                    float4 bb = b4[lane + 32 * m];
                    float4 o_;
                    o_.x = (acc[m].x - mean) * rstd * g.x + bb.x;
                    o_.y = (acc[m].y - mean) * rstd * g.y + bb.y;
                    o_.z = (acc[m].z - mean) * rstd * g.z + bb.z;
                    o_.w = (acc[m].w - mean) * rstd * g.w + bb.w;
                    op[lane + 32 * m] = o_;
                }
            }
        }
        __syncthreads();
    }
}

extern "C" void kernel_launch(void* const* d_in, const int* in_sizes, int n_in,
                              void* d_out, int out_size)
{
    const float* h     = (const float*)d_in[0];
    const float* la    = (const float*)d_in[1];
    const float* gamma = (const float*)d_in[2];
    const float* beta  = (const float*)d_in[3];
    const float* pu    = (const float*)d_in[4];
    const float* pv    = (const float*)d_in[5];
    const int*   ids   = (const int*)d_in[6];
    float*       out   = (float*)d_out;

    zero_cnt_kernel<<<1, NAG>>>();
    build_lists_kernel<<<(BTOK + 255) / 256, 256>>>(ids);

    cudaFuncSetAttribute(div_inject_kernel,
                         cudaFuncAttributeMaxDynamicSharedMemorySize, SMEM_BYTES);
    div_inject_kernel<<<NAG, NTH, SMEM_BYTES>>>(h, la, gamma, beta, pu, pv, out);
}